// round 12
// baseline (speedup 1.0000x reference)
#include <cuda_runtime.h>
#include <cuda_fp16.h>
#include <math.h>
#include <stdint.h>

#define MAX_EDGES 320000

// Weight fragments, B-operand layout for mma.m16n8k16 (col-major B), fp16.
// Entry = uint2 {b0, b1} per lane (k16 B-fragment).
#define FRAG_L1 0
#define FRAG_L2 256
#define FRAG_L3 1280
#define FRAG_L4 2304
#define FRAG_TOTAL 6400
__device__ uint2 g_wfrag[FRAG_TOTAL];

#define MSTRIDE 68   /* floats per staged mix row (64 + 4 pad) */

// ---------------------------------------------------------------------------
// mma.sync m16n8k16 row.col fp16 -> f32  (compute_103-legal, runs on HMMA)
// ---------------------------------------------------------------------------
__device__ __forceinline__ void mma16816(float* c,
                                         uint32_t a0, uint32_t a1, uint32_t a2, uint32_t a3,
                                         uint32_t b0, uint32_t b1) {
    asm volatile(
        "mma.sync.aligned.m16n8k16.row.col.f32.f16.f16.f32 "
        "{%0,%1,%2,%3}, {%4,%5,%6,%7}, {%8,%9}, {%0,%1,%2,%3};"
        : "+f"(c[0]), "+f"(c[1]), "+f"(c[2]), "+f"(c[3])
        : "r"(a0), "r"(a1), "r"(a2), "r"(a3), "r"(b0), "r"(b1));
}

__device__ __forceinline__ void red4(float* p, float a, float b, float c, float d) {
    asm volatile("red.global.add.v4.f32 [%0], {%1,%2,%3,%4};"
                 :: "l"(p), "f"(a), "f"(b), "f"(c), "f"(d) : "memory");
}

// Split (v0,v1) into fp16 hi pair + fp16 residual-lo pair.
__device__ __forceinline__ void split2(float v0, float v1, uint32_t& hi, uint32_t& lo) {
    __half h0 = __float2half_rn(v0);
    __half h1 = __float2half_rn(v1);
    float r0 = v0 - __half2float(h0);
    float r1 = v1 - __half2float(h1);
    __half l0 = __float2half_rn(r0);
    __half l1 = __float2half_rn(r1);
    hi = (uint32_t)__half_as_ushort(h0) | ((uint32_t)__half_as_ushort(h1) << 16);
    lo = (uint32_t)__half_as_ushort(l0) | ((uint32_t)__half_as_ushort(l1) << 16);
}

__device__ __forceinline__ float silu_act(float x, float act) {
    return __fdividef(x, 1.0f + __expf(-x)) * act;
}

// ---------------------------------------------------------------------------
// Setup: fp32 weights -> fragment-ordered fp16 (scales folded).
// L4: columns PERMUTED (lane t owns 16 consecutive channels) AND the message
// normalization 1/sqrt(16) is folded into the weight scale.
// ---------------------------------------------------------------------------
__global__ void build_frags(const float* __restrict__ w0, const float* __restrict__ w1,
                            const float* __restrict__ w2, const float* __restrict__ w3)
{
    int idx = blockIdx.x * blockDim.x + threadIdx.x;
    if (idx >= FRAG_TOTAL) return;

    const float* src; int K, N, ktiles, base; float scale;
    if (idx < FRAG_L2)      { base = FRAG_L1; src = w0; K = 8;  N = 64;  ktiles = 1; scale = 0.35355339059327373f; }
    else if (idx < FRAG_L3) { base = FRAG_L2; src = w1; K = 64; N = 64;  ktiles = 4; scale = 0.125f; }
    else if (idx < FRAG_L4) { base = FRAG_L3; src = w2; K = 64; N = 64;  ktiles = 4; scale = 0.125f; }
    else                    { base = FRAG_L4; src = w3; K = 64; N = 256; ktiles = 4; scale = 0.125f * 0.25f; }

    int fid  = idx - base;
    int lane = fid & 31, pair = fid >> 5;
    int kt = pair % ktiles, nt = pair / ktiles;
    int g = lane >> 2, t = lane & 3;

    int n;
    if (base == FRAG_L4) {
        int chunk = nt >> 3, nt_in = nt & 7;
        n = chunk * 64 + ((g >> 1) << 4) + nt_in * 2 + (g & 1);  // permuted
    } else {
        n = nt * 8 + g;
    }

    int kb = kt * 16 + 2 * t;
    int ks[4] = { kb, kb + 1, kb + 8, kb + 9 };

    uint16_t h[4];
#pragma unroll
    for (int i = 0; i < 4; i++) {
        float v = (ks[i] < K) ? src[ks[i] * N + n] * scale : 0.0f;
        h[i] = __half_as_ushort(__float2half_rn(v));
    }
    uint2 o;
    o.x = (uint32_t)h[0] | ((uint32_t)h[1] << 16);
    o.y = (uint32_t)h[2] | ((uint32_t)h[3] << 16);
    g_wfrag[idx] = o;
}

// ---------------------------------------------------------------------------
// Fused kernel helpers
// ---------------------------------------------------------------------------
__device__ __forceinline__ void act_split(const float* acc, uint32_t* ah, uint32_t* al,
                                          float act) {
#pragma unroll
    for (int kt = 0; kt < 4; kt++) {
        const float* T0 = acc + (2 * kt) * 4;
        const float* T1 = acc + (2 * kt + 1) * 4;
        split2(silu_act(T0[0], act), silu_act(T0[1], act), ah[kt * 4 + 0], al[kt * 4 + 0]);
        split2(silu_act(T0[2], act), silu_act(T0[3], act), ah[kt * 4 + 1], al[kt * 4 + 1]);
        split2(silu_act(T1[0], act), silu_act(T1[1], act), ah[kt * 4 + 2], al[kt * 4 + 2]);
        split2(silu_act(T1[2], act), silu_act(T1[3], act), ah[kt * 4 + 3], al[kt * 4 + 3]);
    }
}

// Layer-4 chunk: 8 MMAs -> stage 16x64 mix tile in warp-private smem ->
// half-warp-per-edge coalesced gather + red.v4 scatter. Only __syncwarp.
template <int CHUNK>
__device__ __forceinline__ void process_chunk(
    const uint32_t* ah, const uint32_t* al, int lane, int t, int g,
    float* wmsg,                             // warp-private [16][MSTRIDE]
    const ulonglong2* sptr,                  // warp-offset: {nrow, orow} per edge
    const float4* sev,                       // warp-offset: {ev0,ev1,ev2,_}
    int edges_left,
    const float* __restrict__ node_feats, float* __restrict__ out)
{
    float acc[32];
#pragma unroll
    for (int i = 0; i < 32; i++) acc[i] = 0.f;
#pragma unroll
    for (int nt = 0; nt < 8; nt++) {
#pragma unroll
        for (int kt = 0; kt < 4; kt++) {
            uint2 f = __ldg(&g_wfrag[FRAG_L4 + ((CHUNK * 8 + nt) * 4 + kt) * 32 + lane]);
            float* c = &acc[nt * 4];
            const uint32_t* A = &ah[kt * 4];
            const uint32_t* L = &al[kt * 4];
            mma16816(c, A[0], A[1], A[2], A[3], f.x, f.y);
            mma16816(c, L[0], L[1], L[2], L[3], f.x, f.y);
        }
    }

    // Stage: lane owns channels t*16+4q..+3 for rows g and g+8.
    __syncwarp();
#pragma unroll
    for (int q = 0; q < 4; q++) {
        *(float4*)&wmsg[g * MSTRIDE + t * 16 + 4 * q] =
            make_float4(acc[8 * q + 0], acc[8 * q + 1], acc[8 * q + 4], acc[8 * q + 5]);
        *(float4*)&wmsg[(g + 8) * MSTRIDE + t * 16 + 4 * q] =
            make_float4(acc[8 * q + 2], acc[8 * q + 3], acc[8 * q + 6], acc[8 * q + 7]);
    }
    __syncwarp();

    const float IS3 = 0.57735026918962576f;     // 1/sqrt(3)
    int half = lane >> 4;
    int l = lane & 15;

#pragma unroll 1
    for (int p = 0; p < 8; p++) {
        int el = 2 * p + half;                  // edge row within warp tile
        bool evalid = el < edges_left;
        ulonglong2 pr = sptr[el];
        const float* nrow = (const float*)pr.x;
        float* orow = (float*)pr.y;
        float4 ev = sev[el];
        float4 mx = *(const float4*)&wmsg[el * MSTRIDE + 4 * l];

        if (CHUNK == 0) {
            float4 ms = __ldg((const float4*)(nrow + 4 * l));
            if (evalid)
                red4(orow + 4 * l, ms.x * mx.x, ms.y * mx.y, ms.z * mx.z, ms.w * mx.w);
        } else if (CHUNK == 1) {
            const float4* vp = (const float4*)(nrow + 64 + 12 * l);
            float4 va = __ldg(vp), vb = __ldg(vp + 1), vc = __ldg(vp + 2);
            float t0 = (va.x * ev.x + va.y * ev.y + va.z * ev.z) * IS3;
            float t1 = (va.w * ev.x + vb.x * ev.y + vb.y * ev.z) * IS3;
            float t2 = (vb.z * ev.x + vb.w * ev.y + vc.x * ev.z) * IS3;
            float t3 = (vc.y * ev.x + vc.z * ev.y + vc.w * ev.z) * IS3;
            if (evalid)
                red4(orow + 64 + 4 * l, t0 * mx.x, t1 * mx.y, t2 * mx.z, t3 * mx.w);
        } else if (CHUNK == 2) {
            const float4* vp = (const float4*)(nrow + 64 + 12 * l);
            float4 va = __ldg(vp), vb = __ldg(vp + 1), vc = __ldg(vp + 2);
            float* po = orow + 128 + 12 * l;
            if (evalid) {
                red4(po,     va.x * mx.x, va.y * mx.x, va.z * mx.x, va.w * mx.y);
                red4(po + 4, vb.x * mx.y, vb.y * mx.y, vb.z * mx.z, vb.w * mx.z);
                red4(po + 8, vc.x * mx.z, vc.y * mx.w, vc.z * mx.w, vc.w * mx.w);
            }
        } else {
            float4 ms = __ldg((const float4*)(nrow + 4 * l));
            float d0 = ms.x * mx.x, d1 = ms.y * mx.y, d2 = ms.z * mx.z, d3 = ms.w * mx.w;
            float* po = orow + 320 + 12 * l;
            if (evalid) {
                red4(po,     d0 * ev.x, d0 * ev.y, d0 * ev.z, d1 * ev.x);
                red4(po + 4, d1 * ev.y, d1 * ev.z, d2 * ev.x, d2 * ev.y);
                red4(po + 8, d2 * ev.z, d3 * ev.x, d3 * ev.y, d3 * ev.z);
            }
        }
    }
}

// ---------------------------------------------------------------------------
// Fused kernel: MLP (chained warp MMAs, fp16 2-term) + coalesced scatter-add.
// Block = 128 threads = 4 warps = 64 edges (16 per warp).
// ---------------------------------------------------------------------------
__global__ void __launch_bounds__(128, 6)
fused_kernel(const float* __restrict__ edge_attrs,
             const float* __restrict__ node_feats,
             const int* __restrict__ senders,
             const int* __restrict__ receivers,
             float* __restrict__ out,
             int n_edges, float act)
{
    __shared__ float      smsg[4][16 * MSTRIDE];
    __shared__ ulonglong2 sptr[64];             // {nrow ptr, orow ptr}
    __shared__ float4     sev[64];              // {ev0, ev1, ev2, 0}

    int tid = threadIdx.x, lane = tid & 31, warp = tid >> 5;
    int g = lane >> 2, t = lane & 3;
    int wbase = blockIdx.x * 64 + warp * 16;
    if (wbase >= n_edges) return;               // whole-warp tail exit
    int e0 = wbase + g, e1 = e0 + 8;
    bool valid0 = e0 < n_edges, valid1 = e1 < n_edges;

    // Each warp loads its own 16 edges' metadata (warp-local, no block sync).
    if (lane < 16) {
        int e = wbase + lane;
        int el = warp * 16 + lane;
        if (e < n_edges) {
            long long s = __ldg(senders + e);
            long long r = __ldg(receivers + e);
            sptr[el] = make_ulonglong2((unsigned long long)(node_feats + s * 256),
                                       (unsigned long long)(out + r * 512));
            const float* ea = edge_attrs + (size_t)e * 11;
            sev[el] = make_float4(__ldg(ea + 8), __ldg(ea + 9), __ldg(ea + 10), 0.f);
        } else {
            sptr[el] = make_ulonglong2((unsigned long long)node_feats,
                                       (unsigned long long)out);
            sev[el] = make_float4(0.f, 0.f, 0.f, 0.f);
        }
    }
    __syncwarp();

    // ---- Layer 1 A fragments from edge_attrs (K=8, cols 8..15 zero) ----
    float x00 = 0.f, x01 = 0.f, x10 = 0.f, x11 = 0.f;
    if (valid0) {
        const float* p = edge_attrs + (size_t)e0 * 11 + 2 * t;
        x00 = __ldg(p); x01 = __ldg(p + 1);
    }
    if (valid1) {
        const float* p = edge_attrs + (size_t)e1 * 11 + 2 * t;
        x10 = __ldg(p); x11 = __ldg(p + 1);
    }
    uint32_t a0h, a0l, a1h, a1l;
    split2(x00, x01, a0h, a0l);
    split2(x10, x11, a1h, a1l);

    float acc[32];
    uint32_t ah[16], al[16];

    // ---- Layer 1: N=64, single k-tile ----
#pragma unroll
    for (int i = 0; i < 32; i++) acc[i] = 0.f;
#pragma unroll
    for (int nt = 0; nt < 8; nt++) {
        uint2 f = __ldg(&g_wfrag[FRAG_L1 + nt * 32 + lane]);
        float* c = &acc[nt * 4];
        mma16816(c, a0h, a1h, 0u, 0u, f.x, f.y);
        mma16816(c, a0l, a1l, 0u, 0u, f.x, f.y);
    }
    act_split(acc, ah, al, act);

    // ---- Layer 2: 64x64 ----
#pragma unroll
    for (int i = 0; i < 32; i++) acc[i] = 0.f;
#pragma unroll
    for (int nt = 0; nt < 8; nt++) {
#pragma unroll
        for (int kt = 0; kt < 4; kt++) {
            uint2 f = __ldg(&g_wfrag[FRAG_L2 + (nt * 4 + kt) * 32 + lane]);
            float* c = &acc[nt * 4];
            const uint32_t* A = &ah[kt * 4];
            const uint32_t* L = &al[kt * 4];
            mma16816(c, A[0], A[1], A[2], A[3], f.x, f.y);
            mma16816(c, L[0], L[1], L[2], L[3], f.x, f.y);
        }
    }
    act_split(acc, ah, al, act);

    // ---- Layer 3: 64x64 ----
#pragma unroll
    for (int i = 0; i < 32; i++) acc[i] = 0.f;
#pragma unroll
    for (int nt = 0; nt < 8; nt++) {
#pragma unroll
        for (int kt = 0; kt < 4; kt++) {
            uint2 f = __ldg(&g_wfrag[FRAG_L3 + (nt * 4 + kt) * 32 + lane]);
            float* c = &acc[nt * 4];
            const uint32_t* A = &ah[kt * 4];
            const uint32_t* L = &al[kt * 4];
            mma16816(c, A[0], A[1], A[2], A[3], f.x, f.y);
            mma16816(c, L[0], L[1], L[2], L[3], f.x, f.y);
        }
    }
    act_split(acc, ah, al, act);

    // ---- Layer 4 chunks: MMA + staged coalesced scatter, warp-independent ----
    float* wmsg = smsg[warp];
    const ulonglong2* wptr = sptr + warp * 16;
    const float4*     wev  = sev  + warp * 16;
    int edges_left = n_edges - wbase;
    process_chunk<0>(ah, al, lane, t, g, wmsg, wptr, wev, edges_left, node_feats, out);
    process_chunk<1>(ah, al, lane, t, g, wmsg, wptr, wev, edges_left, node_feats, out);
    process_chunk<2>(ah, al, lane, t, g, wmsg, wptr, wev, edges_left, node_feats, out);
    process_chunk<3>(ah, al, lane, t, g, wmsg, wptr, wev, edges_left, node_feats, out);
}

// ---------------------------------------------------------------------------
// Host
// ---------------------------------------------------------------------------
static float compute_act_cst() {
    const int    N = 20000;
    const double a = -14.0, b = 14.0;
    const double h = (b - a) / N;
    double sum = 0.0;
    for (int i = 0; i <= N; i++) {
        double xx  = a + h * i;
        double sig = 1.0 / (1.0 + exp(-xx));
        double sl  = xx * sig;
        double f   = exp(-0.5 * xx * xx) * sl * sl;
        double wq  = (i == 0 || i == N) ? 1.0 : ((i & 1) ? 4.0 : 2.0);
        sum += wq * f;
    }
    sum *= h / 3.0;
    sum /= sqrt(2.0 * M_PI);
    return (float)(1.0 / sqrt(sum));
}

extern "C" void kernel_launch(void* const* d_in, const int* in_sizes, int n_in,
                              void* d_out, int out_size)
{
    const float* node_feats = (const float*)d_in[0];
    const float* edge_attrs = (const float*)d_in[1];
    const int*   senders    = (const int*)d_in[2];
    const int*   receivers  = (const int*)d_in[3];
    const float* w0         = (const float*)d_in[4];
    const float* w1         = (const float*)d_in[5];
    const float* w2         = (const float*)d_in[6];
    const float* w3         = (const float*)d_in[7];
    float*       out        = (float*)d_out;

    int n_edges = in_sizes[2];
    if (n_edges > MAX_EDGES) n_edges = MAX_EDGES;

    float act = compute_act_cst();

    cudaMemsetAsync(d_out, 0, (size_t)out_size * sizeof(float));

    build_frags<<<(FRAG_TOTAL + 255) / 256, 256>>>(w0, w1, w2, w3);

    int blocks = (n_edges + 63) / 64;
    fused_kernel<<<blocks, 128>>>(edge_attrs, node_feats, senders,
                                  receivers, out, n_edges, act);
}

// round 13
// speedup vs baseline: 1.0297x; 1.0297x over previous
#include <cuda_runtime.h>
#include <cuda_fp16.h>
#include <math.h>
#include <stdint.h>

#define MAX_EDGES 320000

// Weight fragments, B-operand layout for mma.m16n8k16 (col-major B), fp16.
// Entry = uint2 {b0, b1} per lane (k16 B-fragment).
#define FRAG_L1 0
#define FRAG_L2 256
#define FRAG_L3 1280
#define FRAG_L4 2304
#define FRAG_TOTAL 6400
__device__ uint2 g_wfrag[FRAG_TOTAL];

#define MSTRIDE 68   /* floats per staged mix row (64 + 4 pad) */

// ---------------------------------------------------------------------------
// mma.sync m16n8k16 row.col fp16 -> f32  (compute_103-legal, runs on HMMA)
// ---------------------------------------------------------------------------
__device__ __forceinline__ void mma16816(float* c,
                                         uint32_t a0, uint32_t a1, uint32_t a2, uint32_t a3,
                                         uint32_t b0, uint32_t b1) {
    asm volatile(
        "mma.sync.aligned.m16n8k16.row.col.f32.f16.f16.f32 "
        "{%0,%1,%2,%3}, {%4,%5,%6,%7}, {%8,%9}, {%0,%1,%2,%3};"
        : "+f"(c[0]), "+f"(c[1]), "+f"(c[2]), "+f"(c[3])
        : "r"(a0), "r"(a1), "r"(a2), "r"(a3), "r"(b0), "r"(b1));
}

__device__ __forceinline__ void red4(float* p, float a, float b, float c, float d) {
    asm volatile("red.global.add.v4.f32 [%0], {%1,%2,%3,%4};"
                 :: "l"(p), "f"(a), "f"(b), "f"(c), "f"(d) : "memory");
}

// Split (v0,v1) into fp16 hi pair + fp16 residual-lo pair.
__device__ __forceinline__ void split2(float v0, float v1, uint32_t& hi, uint32_t& lo) {
    __half h0 = __float2half_rn(v0);
    __half h1 = __float2half_rn(v1);
    float r0 = v0 - __half2float(h0);
    float r1 = v1 - __half2float(h1);
    __half l0 = __float2half_rn(r0);
    __half l1 = __float2half_rn(r1);
    hi = (uint32_t)__half_as_ushort(h0) | ((uint32_t)__half_as_ushort(h1) << 16);
    lo = (uint32_t)__half_as_ushort(l0) | ((uint32_t)__half_as_ushort(l1) << 16);
}

__device__ __forceinline__ float silu_act(float x, float act) {
    return __fdividef(x, 1.0f + __expf(-x)) * act;
}

// ---------------------------------------------------------------------------
// Setup: fp32 weights -> fragment-ordered fp16 (scales folded).
// L4: columns PERMUTED (lane t owns 16 consecutive channels) AND the message
// normalization 1/sqrt(16) is folded into the weight scale.
// ---------------------------------------------------------------------------
__global__ void build_frags(const float* __restrict__ w0, const float* __restrict__ w1,
                            const float* __restrict__ w2, const float* __restrict__ w3)
{
    int idx = blockIdx.x * blockDim.x + threadIdx.x;
    if (idx >= FRAG_TOTAL) return;

    const float* src; int K, N, ktiles, base; float scale;
    if (idx < FRAG_L2)      { base = FRAG_L1; src = w0; K = 8;  N = 64;  ktiles = 1; scale = 0.35355339059327373f; }
    else if (idx < FRAG_L3) { base = FRAG_L2; src = w1; K = 64; N = 64;  ktiles = 4; scale = 0.125f; }
    else if (idx < FRAG_L4) { base = FRAG_L3; src = w2; K = 64; N = 64;  ktiles = 4; scale = 0.125f; }
    else                    { base = FRAG_L4; src = w3; K = 64; N = 256; ktiles = 4; scale = 0.125f * 0.25f; }

    int fid  = idx - base;
    int lane = fid & 31, pair = fid >> 5;
    int kt = pair % ktiles, nt = pair / ktiles;
    int g = lane >> 2, t = lane & 3;

    int n;
    if (base == FRAG_L4) {
        int chunk = nt >> 3, nt_in = nt & 7;
        n = chunk * 64 + ((g >> 1) << 4) + nt_in * 2 + (g & 1);  // permuted
    } else {
        n = nt * 8 + g;
    }

    int kb = kt * 16 + 2 * t;
    int ks[4] = { kb, kb + 1, kb + 8, kb + 9 };

    uint16_t h[4];
#pragma unroll
    for (int i = 0; i < 4; i++) {
        float v = (ks[i] < K) ? src[ks[i] * N + n] * scale : 0.0f;
        h[i] = __half_as_ushort(__float2half_rn(v));
    }
    uint2 o;
    o.x = (uint32_t)h[0] | ((uint32_t)h[1] << 16);
    o.y = (uint32_t)h[2] | ((uint32_t)h[3] << 16);
    g_wfrag[idx] = o;
}

// ---------------------------------------------------------------------------
// Fused kernel helpers
// ---------------------------------------------------------------------------
__device__ __forceinline__ void act_split(const float* acc, uint32_t* ah, uint32_t* al,
                                          float act) {
#pragma unroll
    for (int kt = 0; kt < 4; kt++) {
        const float* T0 = acc + (2 * kt) * 4;
        const float* T1 = acc + (2 * kt + 1) * 4;
        split2(silu_act(T0[0], act), silu_act(T0[1], act), ah[kt * 4 + 0], al[kt * 4 + 0]);
        split2(silu_act(T0[2], act), silu_act(T0[3], act), ah[kt * 4 + 1], al[kt * 4 + 1]);
        split2(silu_act(T1[0], act), silu_act(T1[1], act), ah[kt * 4 + 2], al[kt * 4 + 2]);
        split2(silu_act(T1[2], act), silu_act(T1[3], act), ah[kt * 4 + 3], al[kt * 4 + 3]);
    }
}

// Layer-4 chunk: 8 MMAs -> stage 16x64 mix tile in warp-private smem ->
// half-warp-per-edge coalesced gather + red.v4 scatter. Only __syncwarp.
template <int CHUNK>
__device__ __forceinline__ void process_chunk(
    const uint32_t* ah, const uint32_t* al, int lane, int t, int g,
    float* wmsg,                             // warp-private [16][MSTRIDE]
    const ulonglong2* sptr,                  // warp-offset: {nrow, orow} per edge
    const float4* sev,                       // warp-offset: {ev0,ev1,ev2,_}
    int edges_left,
    const float* __restrict__ node_feats, float* __restrict__ out)
{
    float acc[32];
#pragma unroll
    for (int i = 0; i < 32; i++) acc[i] = 0.f;
#pragma unroll
    for (int nt = 0; nt < 8; nt++) {
#pragma unroll
        for (int kt = 0; kt < 4; kt++) {
            uint2 f = __ldg(&g_wfrag[FRAG_L4 + ((CHUNK * 8 + nt) * 4 + kt) * 32 + lane]);
            float* c = &acc[nt * 4];
            const uint32_t* A = &ah[kt * 4];
            const uint32_t* L = &al[kt * 4];
            mma16816(c, A[0], A[1], A[2], A[3], f.x, f.y);
            mma16816(c, L[0], L[1], L[2], L[3], f.x, f.y);
        }
    }

    // Stage: lane owns channels t*16+4q..+3 for rows g and g+8.
    __syncwarp();
#pragma unroll
    for (int q = 0; q < 4; q++) {
        *(float4*)&wmsg[g * MSTRIDE + t * 16 + 4 * q] =
            make_float4(acc[8 * q + 0], acc[8 * q + 1], acc[8 * q + 4], acc[8 * q + 5]);
        *(float4*)&wmsg[(g + 8) * MSTRIDE + t * 16 + 4 * q] =
            make_float4(acc[8 * q + 2], acc[8 * q + 3], acc[8 * q + 6], acc[8 * q + 7]);
    }
    __syncwarp();

    const float IS3 = 0.57735026918962576f;     // 1/sqrt(3)
    int half = lane >> 4;
    int l = lane & 15;

    // Software-pipelined over 8 edge pairs: prefetch next pointers/ev.
    ulonglong2 pr = sptr[half];
    float4 ev = sev[half];
#pragma unroll 1
    for (int p = 0; p < 8; p++) {
        int el = 2 * p + half;                  // edge row within warp tile
        bool evalid = el < edges_left;
        const float* nrow = (const float*)pr.x;
        float* orow = (float*)pr.y;
        float4 mx = *(const float4*)&wmsg[el * MSTRIDE + 4 * l];

        ulonglong2 prn;
        float4 evn;
        if (p < 7) { prn = sptr[el + 2]; evn = sev[el + 2]; }

        if (CHUNK == 0) {
            float4 ms = __ldg((const float4*)(nrow + 4 * l));
            if (evalid)
                red4(orow + 4 * l, ms.x * mx.x, ms.y * mx.y, ms.z * mx.z, ms.w * mx.w);
        } else if (CHUNK == 1) {
            const float4* vp = (const float4*)(nrow + 64 + 12 * l);
            float4 va = __ldg(vp), vb = __ldg(vp + 1), vc = __ldg(vp + 2);
            float t0 = (va.x * ev.x + va.y * ev.y + va.z * ev.z) * IS3;
            float t1 = (va.w * ev.x + vb.x * ev.y + vb.y * ev.z) * IS3;
            float t2 = (vb.z * ev.x + vb.w * ev.y + vc.x * ev.z) * IS3;
            float t3 = (vc.y * ev.x + vc.z * ev.y + vc.w * ev.z) * IS3;
            if (evalid)
                red4(orow + 64 + 4 * l, t0 * mx.x, t1 * mx.y, t2 * mx.z, t3 * mx.w);
        } else if (CHUNK == 2) {
            const float4* vp = (const float4*)(nrow + 64 + 12 * l);
            float4 va = __ldg(vp), vb = __ldg(vp + 1), vc = __ldg(vp + 2);
            float* po = orow + 128 + 12 * l;
            if (evalid) {
                red4(po,     va.x * mx.x, va.y * mx.x, va.z * mx.x, va.w * mx.y);
                red4(po + 4, vb.x * mx.y, vb.y * mx.y, vb.z * mx.z, vb.w * mx.z);
                red4(po + 8, vc.x * mx.z, vc.y * mx.w, vc.z * mx.w, vc.w * mx.w);
            }
        } else {
            float4 ms = __ldg((const float4*)(nrow + 4 * l));
            float d0 = ms.x * mx.x, d1 = ms.y * mx.y, d2 = ms.z * mx.z, d3 = ms.w * mx.w;
            float* po = orow + 320 + 12 * l;
            if (evalid) {
                red4(po,     d0 * ev.x, d0 * ev.y, d0 * ev.z, d1 * ev.x);
                red4(po + 4, d1 * ev.y, d1 * ev.z, d2 * ev.x, d2 * ev.y);
                red4(po + 8, d2 * ev.z, d3 * ev.x, d3 * ev.y, d3 * ev.z);
            }
        }
        pr = prn;
        ev = evn;
    }
}

// ---------------------------------------------------------------------------
// Fused kernel: MLP (chained warp MMAs, fp16 2-term) + coalesced scatter-add.
// Block = 128 threads = 4 warps = 64 edges (16 per warp).
// ---------------------------------------------------------------------------
__global__ void __launch_bounds__(128, 5)
fused_kernel(const float* __restrict__ edge_attrs,
             const float* __restrict__ node_feats,
             const int* __restrict__ senders,
             const int* __restrict__ receivers,
             float* __restrict__ out,
             int n_edges, float act)
{
    __shared__ float      smsg[4][16 * MSTRIDE];
    __shared__ ulonglong2 sptr[64];             // {nrow ptr, orow ptr}
    __shared__ float4     sev[64];              // {ev0, ev1, ev2, 0}

    int tid = threadIdx.x, lane = tid & 31, warp = tid >> 5;
    int g = lane >> 2, t = lane & 3;
    int wbase = blockIdx.x * 64 + warp * 16;
    if (wbase >= n_edges) return;               // whole-warp tail exit
    int e0 = wbase + g, e1 = e0 + 8;
    bool valid0 = e0 < n_edges, valid1 = e1 < n_edges;

    // Each warp loads its own 16 edges' metadata (warp-local, no block sync).
    if (lane < 16) {
        int e = wbase + lane;
        int el = warp * 16 + lane;
        if (e < n_edges) {
            long long s = __ldg(senders + e);
            long long r = __ldg(receivers + e);
            sptr[el] = make_ulonglong2((unsigned long long)(node_feats + s * 256),
                                       (unsigned long long)(out + r * 512));
            const float* ea = edge_attrs + (size_t)e * 11;
            sev[el] = make_float4(__ldg(ea + 8), __ldg(ea + 9), __ldg(ea + 10), 0.f);
        } else {
            sptr[el] = make_ulonglong2((unsigned long long)node_feats,
                                       (unsigned long long)out);
            sev[el] = make_float4(0.f, 0.f, 0.f, 0.f);
        }
    }
    __syncwarp();

    // ---- Layer 1 A fragments from edge_attrs (K=8, cols 8..15 zero) ----
    float x00 = 0.f, x01 = 0.f, x10 = 0.f, x11 = 0.f;
    if (valid0) {
        const float* p = edge_attrs + (size_t)e0 * 11 + 2 * t;
        x00 = __ldg(p); x01 = __ldg(p + 1);
    }
    if (valid1) {
        const float* p = edge_attrs + (size_t)e1 * 11 + 2 * t;
        x10 = __ldg(p); x11 = __ldg(p + 1);
    }
    uint32_t a0h, a0l, a1h, a1l;
    split2(x00, x01, a0h, a0l);
    split2(x10, x11, a1h, a1l);

    float acc[32];
    uint32_t ah[16], al[16];

    // ---- Layer 1: N=64, single k-tile ----
#pragma unroll
    for (int i = 0; i < 32; i++) acc[i] = 0.f;
#pragma unroll
    for (int nt = 0; nt < 8; nt++) {
        uint2 f = __ldg(&g_wfrag[FRAG_L1 + nt * 32 + lane]);
        float* c = &acc[nt * 4];
        mma16816(c, a0h, a1h, 0u, 0u, f.x, f.y);
        mma16816(c, a0l, a1l, 0u, 0u, f.x, f.y);
    }
    act_split(acc, ah, al, act);

    // ---- Layer 2: 64x64 ----
#pragma unroll
    for (int i = 0; i < 32; i++) acc[i] = 0.f;
#pragma unroll
    for (int nt = 0; nt < 8; nt++) {
#pragma unroll
        for (int kt = 0; kt < 4; kt++) {
            uint2 f = __ldg(&g_wfrag[FRAG_L2 + (nt * 4 + kt) * 32 + lane]);
            float* c = &acc[nt * 4];
            const uint32_t* A = &ah[kt * 4];
            const uint32_t* L = &al[kt * 4];
            mma16816(c, A[0], A[1], A[2], A[3], f.x, f.y);
            mma16816(c, L[0], L[1], L[2], L[3], f.x, f.y);
        }
    }
    act_split(acc, ah, al, act);

    // ---- Layer 3: 64x64 ----
#pragma unroll
    for (int i = 0; i < 32; i++) acc[i] = 0.f;
#pragma unroll
    for (int nt = 0; nt < 8; nt++) {
#pragma unroll
        for (int kt = 0; kt < 4; kt++) {
            uint2 f = __ldg(&g_wfrag[FRAG_L3 + (nt * 4 + kt) * 32 + lane]);
            float* c = &acc[nt * 4];
            const uint32_t* A = &ah[kt * 4];
            const uint32_t* L = &al[kt * 4];
            mma16816(c, A[0], A[1], A[2], A[3], f.x, f.y);
            mma16816(c, L[0], L[1], L[2], L[3], f.x, f.y);
        }
    }
    act_split(acc, ah, al, act);

    // ---- Layer 4 chunks: MMA + staged coalesced scatter, warp-independent ----
    float* wmsg = smsg[warp];
    const ulonglong2* wptr = sptr + warp * 16;
    const float4*     wev  = sev  + warp * 16;
    int edges_left = n_edges - wbase;
    process_chunk<0>(ah, al, lane, t, g, wmsg, wptr, wev, edges_left, node_feats, out);
    process_chunk<1>(ah, al, lane, t, g, wmsg, wptr, wev, edges_left, node_feats, out);
    process_chunk<2>(ah, al, lane, t, g, wmsg, wptr, wev, edges_left, node_feats, out);
    process_chunk<3>(ah, al, lane, t, g, wmsg, wptr, wev, edges_left, node_feats, out);
}

// ---------------------------------------------------------------------------
// Host
// ---------------------------------------------------------------------------
static float compute_act_cst() {
    const int    N = 20000;
    const double a = -14.0, b = 14.0;
    const double h = (b - a) / N;
    double sum = 0.0;
    for (int i = 0; i <= N; i++) {
        double xx  = a + h * i;
        double sig = 1.0 / (1.0 + exp(-xx));
        double sl  = xx * sig;
        double f   = exp(-0.5 * xx * xx) * sl * sl;
        double wq  = (i == 0 || i == N) ? 1.0 : ((i & 1) ? 4.0 : 2.0);
        sum += wq * f;
    }
    sum *= h / 3.0;
    sum /= sqrt(2.0 * M_PI);
    return (float)(1.0 / sqrt(sum));
}

extern "C" void kernel_launch(void* const* d_in, const int* in_sizes, int n_in,
                              void* d_out, int out_size)
{
    const float* node_feats = (const float*)d_in[0];
    const float* edge_attrs = (const float*)d_in[1];
    const int*   senders    = (const int*)d_in[2];
    const int*   receivers  = (const int*)d_in[3];
    const float* w0         = (const float*)d_in[4];
    const float* w1         = (const float*)d_in[5];
    const float* w2         = (const float*)d_in[6];
    const float* w3         = (const float*)d_in[7];
    float*       out        = (float*)d_out;

    int n_edges = in_sizes[2];
    if (n_edges > MAX_EDGES) n_edges = MAX_EDGES;

    float act = compute_act_cst();

    cudaMemsetAsync(d_out, 0, (size_t)out_size * sizeof(float));

    build_frags<<<(FRAG_TOTAL + 255) / 256, 256>>>(w0, w1, w2, w3);

    int blocks = (n_edges + 63) / 64;
    fused_kernel<<<blocks, 128>>>(edge_attrs, node_feats, senders,
                                  receivers, out, n_edges, act);
}

// round 15
// speedup vs baseline: 1.1323x; 1.0997x over previous
#include <cuda_runtime.h>
#include <cuda_fp16.h>
#include <math.h>
#include <stdint.h>

#define MAX_EDGES 320000

// Weight fragments, B-operand layout for mma.m16n8k16 (col-major B), fp16.
// Entry = uint2 {b0, b1} per lane (k16 B-fragment).
#define FRAG_L1 0
#define FRAG_L2 256
#define FRAG_L3 1280
#define FRAG_L4 2304
#define FRAG_TOTAL 6400
__device__ uint2 g_wfrag[FRAG_TOTAL];

#define M2 132   /* floats per staged row: two 64-wide chunks + 4 pad */

// ---------------------------------------------------------------------------
// mma.sync m16n8k16 row.col fp16 -> f32  (compute_103-legal, runs on HMMA)
// ---------------------------------------------------------------------------
__device__ __forceinline__ void mma16816(float* c,
                                         uint32_t a0, uint32_t a1, uint32_t a2, uint32_t a3,
                                         uint32_t b0, uint32_t b1) {
    asm volatile(
        "mma.sync.aligned.m16n8k16.row.col.f32.f16.f16.f32 "
        "{%0,%1,%2,%3}, {%4,%5,%6,%7}, {%8,%9}, {%0,%1,%2,%3};"
        : "+f"(c[0]), "+f"(c[1]), "+f"(c[2]), "+f"(c[3])
        : "r"(a0), "r"(a1), "r"(a2), "r"(a3), "r"(b0), "r"(b1));
}

__device__ __forceinline__ void red4(float* p, float a, float b, float c, float d) {
    asm volatile("red.global.add.v4.f32 [%0], {%1,%2,%3,%4};"
                 :: "l"(p), "f"(a), "f"(b), "f"(c), "f"(d) : "memory");
}

// Split (v0,v1) into fp16 hi pair + fp16 residual-lo pair.
__device__ __forceinline__ void split2(float v0, float v1, uint32_t& hi, uint32_t& lo) {
    __half h0 = __float2half_rn(v0);
    __half h1 = __float2half_rn(v1);
    float r0 = v0 - __half2float(h0);
    float r1 = v1 - __half2float(h1);
    __half l0 = __float2half_rn(r0);
    __half l1 = __float2half_rn(r1);
    hi = (uint32_t)__half_as_ushort(h0) | ((uint32_t)__half_as_ushort(h1) << 16);
    lo = (uint32_t)__half_as_ushort(l0) | ((uint32_t)__half_as_ushort(l1) << 16);
}

__device__ __forceinline__ float silu_act(float x, float act) {
    return __fdividef(x, 1.0f + __expf(-x)) * act;
}

// ---------------------------------------------------------------------------
// Setup: fp32 weights -> fragment-ordered fp16 (scales folded).
// L4: columns PERMUTED (lane t owns 16 consecutive channels) AND the message
// normalization 1/sqrt(16) is folded into the weight scale.
// ---------------------------------------------------------------------------
__global__ void build_frags(const float* __restrict__ w0, const float* __restrict__ w1,
                            const float* __restrict__ w2, const float* __restrict__ w3)
{
    int idx = blockIdx.x * blockDim.x + threadIdx.x;
    if (idx >= FRAG_TOTAL) return;

    const float* src; int K, N, ktiles, base; float scale;
    if (idx < FRAG_L2)      { base = FRAG_L1; src = w0; K = 8;  N = 64;  ktiles = 1; scale = 0.35355339059327373f; }
    else if (idx < FRAG_L3) { base = FRAG_L2; src = w1; K = 64; N = 64;  ktiles = 4; scale = 0.125f; }
    else if (idx < FRAG_L4) { base = FRAG_L3; src = w2; K = 64; N = 64;  ktiles = 4; scale = 0.125f; }
    else                    { base = FRAG_L4; src = w3; K = 64; N = 256; ktiles = 4; scale = 0.125f * 0.25f; }

    int fid  = idx - base;
    int lane = fid & 31, pair = fid >> 5;
    int kt = pair % ktiles, nt = pair / ktiles;
    int g = lane >> 2, t = lane & 3;

    int n;
    if (base == FRAG_L4) {
        int chunk = nt >> 3, nt_in = nt & 7;
        n = chunk * 64 + ((g >> 1) << 4) + nt_in * 2 + (g & 1);  // permuted
    } else {
        n = nt * 8 + g;
    }

    int kb = kt * 16 + 2 * t;
    int ks[4] = { kb, kb + 1, kb + 8, kb + 9 };

    uint16_t h[4];
#pragma unroll
    for (int i = 0; i < 4; i++) {
        float v = (ks[i] < K) ? src[ks[i] * N + n] * scale : 0.0f;
        h[i] = __half_as_ushort(__float2half_rn(v));
    }
    uint2 o;
    o.x = (uint32_t)h[0] | ((uint32_t)h[1] << 16);
    o.y = (uint32_t)h[2] | ((uint32_t)h[3] << 16);
    g_wfrag[idx] = o;
}

// ---------------------------------------------------------------------------
// Fused kernel helpers
// ---------------------------------------------------------------------------
__device__ __forceinline__ void act_split(const float* acc, uint32_t* ah, uint32_t* al,
                                          float act) {
#pragma unroll
    for (int kt = 0; kt < 4; kt++) {
        const float* T0 = acc + (2 * kt) * 4;
        const float* T1 = acc + (2 * kt + 1) * 4;
        split2(silu_act(T0[0], act), silu_act(T0[1], act), ah[kt * 4 + 0], al[kt * 4 + 0]);
        split2(silu_act(T0[2], act), silu_act(T0[3], act), ah[kt * 4 + 1], al[kt * 4 + 1]);
        split2(silu_act(T1[0], act), silu_act(T1[1], act), ah[kt * 4 + 2], al[kt * 4 + 2]);
        split2(silu_act(T1[2], act), silu_act(T1[3], act), ah[kt * 4 + 3], al[kt * 4 + 3]);
    }
}

// 8 MMAs for one layer-4 chunk.
template <int CHUNK>
__device__ __forceinline__ void mma_chunk(const uint32_t* ah, const uint32_t* al,
                                          int lane, float* acc)
{
#pragma unroll
    for (int i = 0; i < 32; i++) acc[i] = 0.f;
#pragma unroll
    for (int nt = 0; nt < 8; nt++) {
#pragma unroll
        for (int kt = 0; kt < 4; kt++) {
            uint2 f = __ldg(&g_wfrag[FRAG_L4 + ((CHUNK * 8 + nt) * 4 + kt) * 32 + lane]);
            float* c = &acc[nt * 4];
            const uint32_t* A = &ah[kt * 4];
            const uint32_t* L = &al[kt * 4];
            mma16816(c, A[0], A[1], A[2], A[3], f.x, f.y);
            mma16816(c, L[0], L[1], L[2], L[3], f.x, f.y);
        }
    }
}

// Stage an acc tile: lane owns channels off + t*16 + 4q for rows g, g+8.
__device__ __forceinline__ void stage(const float* acc, float* wmsg, int off,
                                      int g, int t)
{
#pragma unroll
    for (int q = 0; q < 4; q++) {
        *(float4*)&wmsg[g * M2 + off + t * 16 + 4 * q] =
            make_float4(acc[8 * q + 0], acc[8 * q + 1], acc[8 * q + 4], acc[8 * q + 5]);
        *(float4*)&wmsg[(g + 8) * M2 + off + t * 16 + 4 * q] =
            make_float4(acc[8 * q + 2], acc[8 * q + 3], acc[8 * q + 6], acc[8 * q + 7]);
    }
}

// ---------------------------------------------------------------------------
// Fused kernel: MLP (chained warp MMAs, fp16 2-term) + paired-chunk scatter.
// Block = 128 threads = 4 warps = 64 edges (16 per warp).
// ---------------------------------------------------------------------------
__global__ void __launch_bounds__(128, 5)
fused_kernel(const float* __restrict__ edge_attrs,
             const float* __restrict__ node_feats,
             const int* __restrict__ senders,
             const int* __restrict__ receivers,
             float* __restrict__ out,
             int n_edges, float act)
{
    __shared__ float smsg[4][16 * M2];
    __shared__ int   sh_s[64];
    __shared__ int   sh_r[64];
    __shared__ float sh_ev[64 * 3];

    int tid = threadIdx.x, lane = tid & 31, warp = tid >> 5;
    int g = lane >> 2, t = lane & 3;
    int wbase = blockIdx.x * 64 + warp * 16;
    if (wbase >= n_edges) return;               // whole-warp tail exit
    int e0 = wbase + g, e1 = e0 + 8;
    bool valid0 = e0 < n_edges, valid1 = e1 < n_edges;

    // Each warp loads its own 16 edges' metadata (warp-local, no block sync).
    if (lane < 16) {
        int e = wbase + lane;
        int el = warp * 16 + lane;
        if (e < n_edges) {
            sh_s[el] = __ldg(senders + e);
            sh_r[el] = __ldg(receivers + e);
            const float* ea = edge_attrs + (size_t)e * 11;
            sh_ev[el * 3 + 0] = __ldg(ea + 8);
            sh_ev[el * 3 + 1] = __ldg(ea + 9);
            sh_ev[el * 3 + 2] = __ldg(ea + 10);
        } else {
            sh_s[el] = 0; sh_r[el] = 0;
            sh_ev[el * 3 + 0] = 0.f; sh_ev[el * 3 + 1] = 0.f; sh_ev[el * 3 + 2] = 0.f;
        }
    }
    __syncwarp();

    // ---- Layer 1 A fragments from edge_attrs (K=8, cols 8..15 zero) ----
    float x00 = 0.f, x01 = 0.f, x10 = 0.f, x11 = 0.f;
    if (valid0) {
        const float* p = edge_attrs + (size_t)e0 * 11 + 2 * t;
        x00 = __ldg(p); x01 = __ldg(p + 1);
    }
    if (valid1) {
        const float* p = edge_attrs + (size_t)e1 * 11 + 2 * t;
        x10 = __ldg(p); x11 = __ldg(p + 1);
    }
    uint32_t a0h, a0l, a1h, a1l;
    split2(x00, x01, a0h, a0l);
    split2(x10, x11, a1h, a1l);

    float acc[32];
    uint32_t ah[16], al[16];

    // ---- Layer 1: N=64, single k-tile ----
#pragma unroll
    for (int i = 0; i < 32; i++) acc[i] = 0.f;
#pragma unroll
    for (int nt = 0; nt < 8; nt++) {
        uint2 f = __ldg(&g_wfrag[FRAG_L1 + nt * 32 + lane]);
        float* c = &acc[nt * 4];
        mma16816(c, a0h, a1h, 0u, 0u, f.x, f.y);
        mma16816(c, a0l, a1l, 0u, 0u, f.x, f.y);
    }
    act_split(acc, ah, al, act);

    // ---- Layer 2: 64x64 ----
#pragma unroll
    for (int i = 0; i < 32; i++) acc[i] = 0.f;
#pragma unroll
    for (int nt = 0; nt < 8; nt++) {
#pragma unroll
        for (int kt = 0; kt < 4; kt++) {
            uint2 f = __ldg(&g_wfrag[FRAG_L2 + (nt * 4 + kt) * 32 + lane]);
            float* c = &acc[nt * 4];
            const uint32_t* A = &ah[kt * 4];
            const uint32_t* L = &al[kt * 4];
            mma16816(c, A[0], A[1], A[2], A[3], f.x, f.y);
            mma16816(c, L[0], L[1], L[2], L[3], f.x, f.y);
        }
    }
    act_split(acc, ah, al, act);

    // ---- Layer 3: 64x64 ----
#pragma unroll
    for (int i = 0; i < 32; i++) acc[i] = 0.f;
#pragma unroll
    for (int nt = 0; nt < 8; nt++) {
#pragma unroll
        for (int kt = 0; kt < 4; kt++) {
            uint2 f = __ldg(&g_wfrag[FRAG_L3 + (nt * 4 + kt) * 32 + lane]);
            float* c = &acc[nt * 4];
            const uint32_t* A = &ah[kt * 4];
            const uint32_t* L = &al[kt * 4];
            mma16816(c, A[0], A[1], A[2], A[3], f.x, f.y);
            mma16816(c, L[0], L[1], L[2], L[3], f.x, f.y);
        }
    }
    act_split(acc, ah, al, act);

    // ---- Layer 4, paired by gather operand ----
    float* wmsg = smsg[warp];
    const int*   ws  = sh_s  + warp * 16;
    const int*   wr  = sh_r  + warp * 16;
    const float* wev = sh_ev + warp * 48;
    int edges_left = n_edges - wbase;
    const float IS3 = 0.57735026918962576f;     // 1/sqrt(3)
    int half = lane >> 4;
    int l = lane & 15;

    // === Pair A: chunks 0 and 3 (both gather ms = nrow[0:64]) ===
    mma_chunk<0>(ah, al, lane, acc);
    stage(acc, wmsg, 0, g, t);
    mma_chunk<3>(ah, al, lane, acc);
    stage(acc, wmsg, 64, g, t);
    __syncwarp();

#pragma unroll 1
    for (int p = 0; p < 8; p++) {
        int el = 2 * p + half;
        bool evalid = el < edges_left;
        int s = ws[el], r = wr[el];
        float ev0 = wev[el * 3], ev1 = wev[el * 3 + 1], ev2 = wev[el * 3 + 2];
        const float* nrow = node_feats + (size_t)s * 256;
        float* orow = out + (size_t)r * 512;
        float4 mx0 = *(const float4*)&wmsg[el * M2 + 4 * l];
        float4 mx3 = *(const float4*)&wmsg[el * M2 + 64 + 4 * l];
        float4 ms = __ldg((const float4*)(nrow + 4 * l));
        if (evalid) {
            red4(orow + 4 * l, ms.x * mx0.x, ms.y * mx0.y, ms.z * mx0.z, ms.w * mx0.w);
            float d0 = ms.x * mx3.x, d1 = ms.y * mx3.y, d2 = ms.z * mx3.z, d3 = ms.w * mx3.w;
            float* po = orow + 320 + 12 * l;
            red4(po,     d0 * ev0, d0 * ev1, d0 * ev2, d1 * ev0);
            red4(po + 4, d1 * ev1, d1 * ev2, d2 * ev0, d2 * ev1);
            red4(po + 8, d2 * ev2, d3 * ev0, d3 * ev1, d3 * ev2);
        }
    }
    __syncwarp();

    // === Pair B: chunks 1 and 2 (both gather v = nrow[64:256]) ===
    mma_chunk<1>(ah, al, lane, acc);
    stage(acc, wmsg, 0, g, t);
    mma_chunk<2>(ah, al, lane, acc);
    stage(acc, wmsg, 64, g, t);
    __syncwarp();

#pragma unroll 1
    for (int p = 0; p < 8; p++) {
        int el = 2 * p + half;
        bool evalid = el < edges_left;
        int s = ws[el], r = wr[el];
        float ev0 = wev[el * 3], ev1 = wev[el * 3 + 1], ev2 = wev[el * 3 + 2];
        const float* nrow = node_feats + (size_t)s * 256;
        float* orow = out + (size_t)r * 512;
        float4 mx1 = *(const float4*)&wmsg[el * M2 + 4 * l];
        float4 mx2 = *(const float4*)&wmsg[el * M2 + 64 + 4 * l];
        const float4* vp = (const float4*)(nrow + 64 + 12 * l);
        float4 va = __ldg(vp), vb = __ldg(vp + 1), vc = __ldg(vp + 2);
        if (evalid) {
            float t0 = (va.x * ev0 + va.y * ev1 + va.z * ev2) * IS3;
            float t1 = (va.w * ev0 + vb.x * ev1 + vb.y * ev2) * IS3;
            float t2 = (vb.z * ev0 + vb.w * ev1 + vc.x * ev2) * IS3;
            float t3 = (vc.y * ev0 + vc.z * ev1 + vc.w * ev2) * IS3;
            red4(orow + 64 + 4 * l, t0 * mx1.x, t1 * mx1.y, t2 * mx1.z, t3 * mx1.w);
            float* po = orow + 128 + 12 * l;
            red4(po,     va.x * mx2.x, va.y * mx2.x, va.z * mx2.x, va.w * mx2.y);
            red4(po + 4, vb.x * mx2.y, vb.y * mx2.y, vb.z * mx2.z, vb.w * mx2.z);
            red4(po + 8, vc.x * mx2.z, vc.y * mx2.w, vc.z * mx2.w, vc.w * mx2.w);
        }
    }
}

// ---------------------------------------------------------------------------
// Host
// ---------------------------------------------------------------------------
static float compute_act_cst() {
    const int    N = 20000;
    const double a = -14.0, b = 14.0;
    const double h = (b - a) / N;
    double sum = 0.0;
    for (int i = 0; i <= N; i++) {
        double xx  = a + h * i;
        double sig = 1.0 / (1.0 + exp(-xx));
        double sl  = xx * sig;
        double f   = exp(-0.5 * xx * xx) * sl * sl;
        double wq  = (i == 0 || i == N) ? 1.0 : ((i & 1) ? 4.0 : 2.0);
        sum += wq * f;
    }
    sum *= h / 3.0;
    sum /= sqrt(2.0 * M_PI);
    return (float)(1.0 / sqrt(sum));
}

extern "C" void kernel_launch(void* const* d_in, const int* in_sizes, int n_in,
                              void* d_out, int out_size)
{
    const float* node_feats = (const float*)d_in[0];
    const float* edge_attrs = (const float*)d_in[1];
    const int*   senders    = (const int*)d_in[2];
    const int*   receivers  = (const int*)d_in[3];
    const float* w0         = (const float*)d_in[4];
    const float* w1         = (const float*)d_in[5];
    const float* w2         = (const float*)d_in[6];
    const float* w3         = (const float*)d_in[7];
    float*       out        = (float*)d_out;

    int n_edges = in_sizes[2];
    if (n_edges > MAX_EDGES) n_edges = MAX_EDGES;

    float act = compute_act_cst();

    cudaMemsetAsync(d_out, 0, (size_t)out_size * sizeof(float));

    build_frags<<<(FRAG_TOTAL + 255) / 256, 256>>>(w0, w1, w2, w3);

    int blocks = (n_edges + 63) / 64;
    fused_kernel<<<blocks, 128>>>(edge_attrs, node_feats, senders,
                                  receivers, out, n_edges, act);
}

// round 16
// speedup vs baseline: 1.3178x; 1.1638x over previous
#include <cuda_runtime.h>
#include <cuda_fp16.h>
#include <math.h>
#include <stdint.h>

#define MAX_EDGES 320000
#define MAX_NODES 32768

// Weight fragments, B-operand layout for mma.m16n8k16 (col-major B), fp16.
#define FRAG_L1 0
#define FRAG_L2 256
#define FRAG_L3 1280
#define FRAG_L4 2304
#define FRAG_TOTAL 6400
__device__ uint2 g_wfrag[FRAG_TOTAL];

// Counting-sort scratch
__device__ int g_cnt[MAX_NODES];
__device__ int g_cur[MAX_NODES];
__device__ int g_eidx[MAX_EDGES];

#define M2 132   /* floats per staged row: two 64-wide chunks + 4 pad */

// ---------------------------------------------------------------------------
__device__ __forceinline__ void mma16816(float* c,
                                         uint32_t a0, uint32_t a1, uint32_t a2, uint32_t a3,
                                         uint32_t b0, uint32_t b1) {
    asm volatile(
        "mma.sync.aligned.m16n8k16.row.col.f32.f16.f16.f32 "
        "{%0,%1,%2,%3}, {%4,%5,%6,%7}, {%8,%9}, {%0,%1,%2,%3};"
        : "+f"(c[0]), "+f"(c[1]), "+f"(c[2]), "+f"(c[3])
        : "r"(a0), "r"(a1), "r"(a2), "r"(a3), "r"(b0), "r"(b1));
}

__device__ __forceinline__ void red4(float* p, float a, float b, float c, float d) {
    asm volatile("red.global.add.v4.f32 [%0], {%1,%2,%3,%4};"
                 :: "l"(p), "f"(a), "f"(b), "f"(c), "f"(d) : "memory");
}

__device__ __forceinline__ void split2(float v0, float v1, uint32_t& hi, uint32_t& lo) {
    __half h0 = __float2half_rn(v0);
    __half h1 = __float2half_rn(v1);
    float r0 = v0 - __half2float(h0);
    float r1 = v1 - __half2float(h1);
    __half l0 = __float2half_rn(r0);
    __half l1 = __float2half_rn(r1);
    hi = (uint32_t)__half_as_ushort(h0) | ((uint32_t)__half_as_ushort(h1) << 16);
    lo = (uint32_t)__half_as_ushort(l0) | ((uint32_t)__half_as_ushort(l1) << 16);
}

__device__ __forceinline__ float silu_act(float x, float act) {
    return __fdividef(x, 1.0f + __expf(-x)) * act;
}

// ---------------------------------------------------------------------------
// Counting sort by receiver: zero -> hist -> scan -> scatter
// ---------------------------------------------------------------------------
__global__ void zero_kernel(int n) {
    int i = blockIdx.x * blockDim.x + threadIdx.x;
    if (i < n) g_cnt[i] = 0;
}

__global__ void hist_kernel(const int* __restrict__ receivers, int n_edges) {
    int e = blockIdx.x * blockDim.x + threadIdx.x;
    if (e < n_edges) atomicAdd(&g_cnt[receivers[e]], 1);
}

__global__ void scan_kernel(int n) {
    __shared__ int part[1024];
    int tid = threadIdx.x;
    int per = (n + 1023) >> 10;
    int base = tid * per;
    int s = 0;
    for (int i = 0; i < per; i++) {
        int idx = base + i;
        if (idx < n) s += g_cnt[idx];
    }
    part[tid] = s;
    __syncthreads();
    for (int d = 1; d < 1024; d <<= 1) {
        int v = (tid >= d) ? part[tid - d] : 0;
        __syncthreads();
        part[tid] += v;
        __syncthreads();
    }
    int off = (tid == 0) ? 0 : part[tid - 1];
    for (int i = 0; i < per; i++) {
        int idx = base + i;
        if (idx < n) { int c = g_cnt[idx]; g_cur[idx] = off; off += c; }
    }
}

__global__ void scatter_sort_kernel(const int* __restrict__ receivers, int n_edges) {
    int e = blockIdx.x * blockDim.x + threadIdx.x;
    if (e < n_edges) {
        int pos = atomicAdd(&g_cur[receivers[e]], 1);
        g_eidx[pos] = e;
    }
}

// ---------------------------------------------------------------------------
// Setup: fp32 weights -> fragment-ordered fp16 (scales folded).
// L4: columns PERMUTED; 1/sqrt(16) folded in.
// ---------------------------------------------------------------------------
__global__ void build_frags(const float* __restrict__ w0, const float* __restrict__ w1,
                            const float* __restrict__ w2, const float* __restrict__ w3)
{
    int idx = blockIdx.x * blockDim.x + threadIdx.x;
    if (idx >= FRAG_TOTAL) return;

    const float* src; int K, N, ktiles, base; float scale;
    if (idx < FRAG_L2)      { base = FRAG_L1; src = w0; K = 8;  N = 64;  ktiles = 1; scale = 0.35355339059327373f; }
    else if (idx < FRAG_L3) { base = FRAG_L2; src = w1; K = 64; N = 64;  ktiles = 4; scale = 0.125f; }
    else if (idx < FRAG_L4) { base = FRAG_L3; src = w2; K = 64; N = 64;  ktiles = 4; scale = 0.125f; }
    else                    { base = FRAG_L4; src = w3; K = 64; N = 256; ktiles = 4; scale = 0.125f * 0.25f; }

    int fid  = idx - base;
    int lane = fid & 31, pair = fid >> 5;
    int kt = pair % ktiles, nt = pair / ktiles;
    int g = lane >> 2, t = lane & 3;

    int n;
    if (base == FRAG_L4) {
        int chunk = nt >> 3, nt_in = nt & 7;
        n = chunk * 64 + ((g >> 1) << 4) + nt_in * 2 + (g & 1);
    } else {
        n = nt * 8 + g;
    }

    int kb = kt * 16 + 2 * t;
    int ks[4] = { kb, kb + 1, kb + 8, kb + 9 };

    uint16_t h[4];
#pragma unroll
    for (int i = 0; i < 4; i++) {
        float v = (ks[i] < K) ? src[ks[i] * N + n] * scale : 0.0f;
        h[i] = __half_as_ushort(__float2half_rn(v));
    }
    uint2 o;
    o.x = (uint32_t)h[0] | ((uint32_t)h[1] << 16);
    o.y = (uint32_t)h[2] | ((uint32_t)h[3] << 16);
    g_wfrag[idx] = o;
}

// ---------------------------------------------------------------------------
__device__ __forceinline__ void act_split(const float* acc, uint32_t* ah, uint32_t* al,
                                          float act) {
#pragma unroll
    for (int kt = 0; kt < 4; kt++) {
        const float* T0 = acc + (2 * kt) * 4;
        const float* T1 = acc + (2 * kt + 1) * 4;
        split2(silu_act(T0[0], act), silu_act(T0[1], act), ah[kt * 4 + 0], al[kt * 4 + 0]);
        split2(silu_act(T0[2], act), silu_act(T0[3], act), ah[kt * 4 + 1], al[kt * 4 + 1]);
        split2(silu_act(T1[0], act), silu_act(T1[1], act), ah[kt * 4 + 2], al[kt * 4 + 2]);
        split2(silu_act(T1[2], act), silu_act(T1[3], act), ah[kt * 4 + 3], al[kt * 4 + 3]);
    }
}

template <int CHUNK>
__device__ __forceinline__ void mma_chunk(const uint32_t* ah, const uint32_t* al,
                                          int lane, float* acc)
{
#pragma unroll
    for (int i = 0; i < 32; i++) acc[i] = 0.f;
#pragma unroll
    for (int nt = 0; nt < 8; nt++) {
#pragma unroll
        for (int kt = 0; kt < 4; kt++) {
            uint2 f = __ldg(&g_wfrag[FRAG_L4 + ((CHUNK * 8 + nt) * 4 + kt) * 32 + lane]);
            float* c = &acc[nt * 4];
            const uint32_t* A = &ah[kt * 4];
            const uint32_t* L = &al[kt * 4];
            mma16816(c, A[0], A[1], A[2], A[3], f.x, f.y);
            mma16816(c, L[0], L[1], L[2], L[3], f.x, f.y);
        }
    }
}

__device__ __forceinline__ void stage(const float* acc, float* wmsg, int off,
                                      int g, int t)
{
#pragma unroll
    for (int q = 0; q < 4; q++) {
        *(float4*)&wmsg[g * M2 + off + t * 16 + 4 * q] =
            make_float4(acc[8 * q + 0], acc[8 * q + 1], acc[8 * q + 4], acc[8 * q + 5]);
        *(float4*)&wmsg[(g + 8) * M2 + off + t * 16 + 4 * q] =
            make_float4(acc[8 * q + 2], acc[8 * q + 3], acc[8 * q + 6], acc[8 * q + 7]);
    }
}

// ---------------------------------------------------------------------------
// Fused kernel: MLP + paired-chunk scatter with receiver-run merging.
// Edges processed in receiver-sorted order via g_eidx. Half-warp owns 8
// CONTIGUOUS sorted edges -> long same-receiver runs -> merged red4 flushes.
// ---------------------------------------------------------------------------
__global__ void __launch_bounds__(128, 5)
fused_kernel(const float* __restrict__ edge_attrs,
             const float* __restrict__ node_feats,
             const int* __restrict__ senders,
             const int* __restrict__ receivers,
             float* __restrict__ out,
             int n_edges, float act)
{
    __shared__ float smsg[4][16 * M2];
    __shared__ int   sh_e[64];
    __shared__ int   sh_s[64];
    __shared__ int   sh_r[64];
    __shared__ float sh_ev[64 * 3];

    int tid = threadIdx.x, lane = tid & 31, warp = tid >> 5;
    int g = lane >> 2, t = lane & 3;
    int wbase = blockIdx.x * 64 + warp * 16;
    if (wbase >= n_edges) return;

    if (lane < 16) {
        int pos = wbase + lane;
        int el = warp * 16 + lane;
        if (pos < n_edges) {
            int e = __ldg(&g_eidx[pos]);
            sh_e[el] = e;
            sh_s[el] = __ldg(senders + e);
            sh_r[el] = __ldg(receivers + e);
            const float* ea = edge_attrs + (size_t)e * 11;
            sh_ev[el * 3 + 0] = __ldg(ea + 8);
            sh_ev[el * 3 + 1] = __ldg(ea + 9);
            sh_ev[el * 3 + 2] = __ldg(ea + 10);
        } else {
            sh_e[el] = 0; sh_s[el] = 0; sh_r[el] = -1;
            sh_ev[el * 3 + 0] = 0.f; sh_ev[el * 3 + 1] = 0.f; sh_ev[el * 3 + 2] = 0.f;
        }
    }
    __syncwarp();

    // ---- Layer 1 A fragments (K=8, cols 8..15 zero), via sorted edge ids ----
    bool valid0 = (wbase + g)     < n_edges;
    bool valid1 = (wbase + g + 8) < n_edges;
    float x00 = 0.f, x01 = 0.f, x10 = 0.f, x11 = 0.f;
    if (valid0) {
        const float* p = edge_attrs + (size_t)sh_e[warp * 16 + g] * 11 + 2 * t;
        x00 = __ldg(p); x01 = __ldg(p + 1);
    }
    if (valid1) {
        const float* p = edge_attrs + (size_t)sh_e[warp * 16 + g + 8] * 11 + 2 * t;
        x10 = __ldg(p); x11 = __ldg(p + 1);
    }
    uint32_t a0h, a0l, a1h, a1l;
    split2(x00, x01, a0h, a0l);
    split2(x10, x11, a1h, a1l);

    float acc[32];
    uint32_t ah[16], al[16];

    // ---- Layer 1 ----
#pragma unroll
    for (int i = 0; i < 32; i++) acc[i] = 0.f;
#pragma unroll
    for (int nt = 0; nt < 8; nt++) {
        uint2 f = __ldg(&g_wfrag[FRAG_L1 + nt * 32 + lane]);
        float* c = &acc[nt * 4];
        mma16816(c, a0h, a1h, 0u, 0u, f.x, f.y);
        mma16816(c, a0l, a1l, 0u, 0u, f.x, f.y);
    }
    act_split(acc, ah, al, act);

    // ---- Layer 2 ----
#pragma unroll
    for (int i = 0; i < 32; i++) acc[i] = 0.f;
#pragma unroll
    for (int nt = 0; nt < 8; nt++) {
#pragma unroll
        for (int kt = 0; kt < 4; kt++) {
            uint2 f = __ldg(&g_wfrag[FRAG_L2 + (nt * 4 + kt) * 32 + lane]);
            float* c = &acc[nt * 4];
            const uint32_t* A = &ah[kt * 4];
            const uint32_t* L = &al[kt * 4];
            mma16816(c, A[0], A[1], A[2], A[3], f.x, f.y);
            mma16816(c, L[0], L[1], L[2], L[3], f.x, f.y);
        }
    }
    act_split(acc, ah, al, act);

    // ---- Layer 3 ----
#pragma unroll
    for (int i = 0; i < 32; i++) acc[i] = 0.f;
#pragma unroll
    for (int nt = 0; nt < 8; nt++) {
#pragma unroll
        for (int kt = 0; kt < 4; kt++) {
            uint2 f = __ldg(&g_wfrag[FRAG_L3 + (nt * 4 + kt) * 32 + lane]);
            float* c = &acc[nt * 4];
            const uint32_t* A = &ah[kt * 4];
            const uint32_t* L = &al[kt * 4];
            mma16816(c, A[0], A[1], A[2], A[3], f.x, f.y);
            mma16816(c, L[0], L[1], L[2], L[3], f.x, f.y);
        }
    }
    act_split(acc, ah, al, act);

    // ---- Layer 4, paired by gather operand, run-merged atomics ----
    float* wmsg = smsg[warp];
    const int*   ws  = sh_s  + warp * 16;
    const int*   wr  = sh_r  + warp * 16;
    const float* wev = sh_ev + warp * 48;
    int edges_left = n_edges - wbase;
    const float IS3 = 0.57735026918962576f;
    int half = lane >> 4;
    int l = lane & 15;
    int elbase = half * 8;

    // === Pair A: chunks 0 and 3 (both gather ms = nrow[0:64]) ===
    mma_chunk<0>(ah, al, lane, acc);
    stage(acc, wmsg, 0, g, t);
    mma_chunk<3>(ah, al, lane, acc);
    stage(acc, wmsg, 64, g, t);
    __syncwarp();

    {
        float4 aA = make_float4(0.f, 0.f, 0.f, 0.f);
        float4 aB0 = aA, aB1 = aA, aB2 = aA;
        int prevr = -1;
        float* orow = out;
#pragma unroll 1
        for (int p = 0; p < 8; p++) {
            int el = elbase + p;
            if (el >= edges_left) break;
            int r = wr[el];
            if (r != prevr) {
                if (prevr >= 0) {
                    red4(orow + 4 * l, aA.x, aA.y, aA.z, aA.w);
                    float* po = orow + 320 + 12 * l;
                    red4(po,     aB0.x, aB0.y, aB0.z, aB0.w);
                    red4(po + 4, aB1.x, aB1.y, aB1.z, aB1.w);
                    red4(po + 8, aB2.x, aB2.y, aB2.z, aB2.w);
                }
                prevr = r;
                orow = out + (size_t)r * 512;
                aA = make_float4(0.f, 0.f, 0.f, 0.f);
                aB0 = aA; aB1 = aA; aB2 = aA;
            }
            int s = ws[el];
            float ev0 = wev[el * 3], ev1 = wev[el * 3 + 1], ev2 = wev[el * 3 + 2];
            const float* nrow = node_feats + (size_t)s * 256;
            float4 mx0 = *(const float4*)&wmsg[el * M2 + 4 * l];
            float4 mx3 = *(const float4*)&wmsg[el * M2 + 64 + 4 * l];
            float4 ms = __ldg((const float4*)(nrow + 4 * l));
            aA.x += ms.x * mx0.x; aA.y += ms.y * mx0.y;
            aA.z += ms.z * mx0.z; aA.w += ms.w * mx0.w;
            float d0 = ms.x * mx3.x, d1 = ms.y * mx3.y;
            float d2 = ms.z * mx3.z, d3 = ms.w * mx3.w;
            aB0.x += d0 * ev0; aB0.y += d0 * ev1; aB0.z += d0 * ev2; aB0.w += d1 * ev0;
            aB1.x += d1 * ev1; aB1.y += d1 * ev2; aB1.z += d2 * ev0; aB1.w += d2 * ev1;
            aB2.x += d2 * ev2; aB2.y += d3 * ev0; aB2.z += d3 * ev1; aB2.w += d3 * ev2;
        }
        if (prevr >= 0) {
            red4(orow + 4 * l, aA.x, aA.y, aA.z, aA.w);
            float* po = orow + 320 + 12 * l;
            red4(po,     aB0.x, aB0.y, aB0.z, aB0.w);
            red4(po + 4, aB1.x, aB1.y, aB1.z, aB1.w);
            red4(po + 8, aB2.x, aB2.y, aB2.z, aB2.w);
        }
    }
    __syncwarp();

    // === Pair B: chunks 1 and 2 (both gather v = nrow[64:256]) ===
    mma_chunk<1>(ah, al, lane, acc);
    stage(acc, wmsg, 0, g, t);
    mma_chunk<2>(ah, al, lane, acc);
    stage(acc, wmsg, 64, g, t);
    __syncwarp();

    {
        float4 aS = make_float4(0.f, 0.f, 0.f, 0.f);
        float4 aV0 = aS, aV1 = aS, aV2 = aS;
        int prevr = -1;
        float* orow = out;
#pragma unroll 1
        for (int p = 0; p < 8; p++) {
            int el = elbase + p;
            if (el >= edges_left) break;
            int r = wr[el];
            if (r != prevr) {
                if (prevr >= 0) {
                    red4(orow + 64 + 4 * l, aS.x, aS.y, aS.z, aS.w);
                    float* po = orow + 128 + 12 * l;
                    red4(po,     aV0.x, aV0.y, aV0.z, aV0.w);
                    red4(po + 4, aV1.x, aV1.y, aV1.z, aV1.w);
                    red4(po + 8, aV2.x, aV2.y, aV2.z, aV2.w);
                }
                prevr = r;
                orow = out + (size_t)r * 512;
                aS = make_float4(0.f, 0.f, 0.f, 0.f);
                aV0 = aS; aV1 = aS; aV2 = aS;
            }
            int s = ws[el];
            float ev0 = wev[el * 3], ev1 = wev[el * 3 + 1], ev2 = wev[el * 3 + 2];
            const float* nrow = node_feats + (size_t)s * 256;
            float4 mx1 = *(const float4*)&wmsg[el * M2 + 4 * l];
            float4 mx2 = *(const float4*)&wmsg[el * M2 + 64 + 4 * l];
            const float4* vp = (const float4*)(nrow + 64 + 12 * l);
            float4 va = __ldg(vp), vb = __ldg(vp + 1), vc = __ldg(vp + 2);
            float t0 = (va.x * ev0 + va.y * ev1 + va.z * ev2) * IS3;
            float t1 = (va.w * ev0 + vb.x * ev1 + vb.y * ev2) * IS3;
            float t2 = (vb.z * ev0 + vb.w * ev1 + vc.x * ev2) * IS3;
            float t3 = (vc.y * ev0 + vc.z * ev1 + vc.w * ev2) * IS3;
            aS.x += t0 * mx1.x; aS.y += t1 * mx1.y; aS.z += t2 * mx1.z; aS.w += t3 * mx1.w;
            aV0.x += va.x * mx2.x; aV0.y += va.y * mx2.x; aV0.z += va.z * mx2.x; aV0.w += va.w * mx2.y;
            aV1.x += vb.x * mx2.y; aV1.y += vb.y * mx2.y; aV1.z += vb.z * mx2.z; aV1.w += vb.w * mx2.z;
            aV2.x += vc.x * mx2.z; aV2.y += vc.y * mx2.w; aV2.z += vc.z * mx2.w; aV2.w += vc.w * mx2.w;
        }
        if (prevr >= 0) {
            red4(orow + 64 + 4 * l, aS.x, aS.y, aS.z, aS.w);
            float* po = orow + 128 + 12 * l;
            red4(po,     aV0.x, aV0.y, aV0.z, aV0.w);
            red4(po + 4, aV1.x, aV1.y, aV1.z, aV1.w);
            red4(po + 8, aV2.x, aV2.y, aV2.z, aV2.w);
        }
    }
}

// ---------------------------------------------------------------------------
// Host
// ---------------------------------------------------------------------------
static float compute_act_cst() {
    const int    N = 20000;
    const double a = -14.0, b = 14.0;
    const double h = (b - a) / N;
    double sum = 0.0;
    for (int i = 0; i <= N; i++) {
        double xx  = a + h * i;
        double sig = 1.0 / (1.0 + exp(-xx));
        double sl  = xx * sig;
        double f   = exp(-0.5 * xx * xx) * sl * sl;
        double wq  = (i == 0 || i == N) ? 1.0 : ((i & 1) ? 4.0 : 2.0);
        sum += wq * f;
    }
    sum *= h / 3.0;
    sum /= sqrt(2.0 * M_PI);
    return (float)(1.0 / sqrt(sum));
}

extern "C" void kernel_launch(void* const* d_in, const int* in_sizes, int n_in,
                              void* d_out, int out_size)
{
    const float* node_feats = (const float*)d_in[0];
    const float* edge_attrs = (const float*)d_in[1];
    const int*   senders    = (const int*)d_in[2];
    const int*   receivers  = (const int*)d_in[3];
    const float* w0         = (const float*)d_in[4];
    const float* w1         = (const float*)d_in[5];
    const float* w2         = (const float*)d_in[6];
    const float* w3         = (const float*)d_in[7];
    float*       out        = (float*)d_out;

    int n_edges = in_sizes[2];
    if (n_edges > MAX_EDGES) n_edges = MAX_EDGES;
    int n_nodes = out_size / 512;
    if (n_nodes > MAX_NODES) n_nodes = MAX_NODES;

    float act = compute_act_cst();

    cudaMemsetAsync(d_out, 0, (size_t)out_size * sizeof(float));

    build_frags<<<(FRAG_TOTAL + 255) / 256, 256>>>(w0, w1, w2, w3);

    // Counting sort of edges by receiver -> g_eidx
    zero_kernel<<<(n_nodes + 255) / 256, 256>>>(n_nodes);
    hist_kernel<<<(n_edges + 255) / 256, 256>>>(receivers, n_edges);
    scan_kernel<<<1, 1024>>>(n_nodes);
    scatter_sort_kernel<<<(n_edges + 255) / 256, 256>>>(receivers, n_edges);

    int blocks = (n_edges + 63) / 64;
    fused_kernel<<<blocks, 128>>>(edge_attrs, node_feats, senders,
                                  receivers, out, n_edges, act);
}